// round 1
// baseline (speedup 1.0000x reference)
#include <cuda_runtime.h>
#include <cuda_bf16.h>
#include <math.h>

// Problem constants
#define B_DIM     32
#define S_DIM     2048
#define ROWS      (B_DIM * S_DIM)      // 65536
#define F_DIM     8
#define E_DIM     8
#define D_NODE    128
#define D_T2V     64                    // F*E
#define D_K       (D_NODE + D_T2V)      // 192: hot matvec depth
#define D_OUT     64
#define N_BT      64
#define N_ET      50
#define N_EQ      100

// proj_w row offsets per segment
#define OFF_BT    192
#define OFF_POP   224
#define OFF_ET    240
#define OFF_EQ    272

// Scratch (no cudaMalloc allowed)
__device__ float g_counts_sum[S_DIM];
__device__ float g_btype_proj[N_BT * D_OUT];
__device__ float g_etype_proj[N_ET * D_OUT];
__device__ float g_equip_proj[N_EQ * D_OUT];
__device__ float g_pv0[D_OUT];   // pop_w @ W_pop
__device__ float g_pv1[D_OUT];   // pop_b @ W_pop + proj_b

// ---------------------------------------------------------------------------
// Precompute 1: counts_sum[s] = sum_b building_counts[b, s]
// ---------------------------------------------------------------------------
__global__ void counts_kernel(const float* __restrict__ counts) {
    int s = blockIdx.x * blockDim.x + threadIdx.x;
    if (s < S_DIM) {
        float a = 0.f;
        #pragma unroll
        for (int b = 0; b < B_DIM; ++b) a += counts[b * S_DIM + s];
        g_counts_sum[s] = a;
    }
}

// ---------------------------------------------------------------------------
// Precompute 2: project small-vocab tables into output space (64-dim)
// grid = 64 + 50 + 100 + 1 = 215 blocks of 64 threads
// ---------------------------------------------------------------------------
__global__ void precompute_tables(const float* __restrict__ btype_table,
                                  const float* __restrict__ etype_table,
                                  const float* __restrict__ equip_table,
                                  const float* __restrict__ pop_w,
                                  const float* __restrict__ pop_b,
                                  const float* __restrict__ proj_w,
                                  const float* __restrict__ proj_b) {
    int j = threadIdx.x;                 // output dim 0..63
    int n = blockIdx.x;
    if (n < N_BT) {
        float a = 0.f;
        #pragma unroll
        for (int d = 0; d < 32; ++d)
            a += btype_table[n * 32 + d] * proj_w[(OFF_BT + d) * D_OUT + j];
        g_btype_proj[n * D_OUT + j] = a;
    } else if (n < N_BT + N_ET) {
        int m = n - N_BT;
        float a = 0.f;
        #pragma unroll
        for (int d = 0; d < 32; ++d)
            a += etype_table[m * 32 + d] * proj_w[(OFF_ET + d) * D_OUT + j];
        g_etype_proj[m * D_OUT + j] = a;
    } else if (n < N_BT + N_ET + N_EQ) {
        int m = n - N_BT - N_ET;
        float a = 0.f;
        #pragma unroll
        for (int d = 0; d < 32; ++d)
            a += equip_table[m * 32 + d] * proj_w[(OFF_EQ + d) * D_OUT + j];
        g_equip_proj[m * D_OUT + j] = a;
    } else {
        float a0 = 0.f, a1 = 0.f;
        #pragma unroll
        for (int d = 0; d < 16; ++d) {
            float w = proj_w[(OFF_POP + d) * D_OUT + j];
            a0 += pop_w[d] * w;
            a1 += pop_b[d] * w;
        }
        g_pv0[j] = a0;
        g_pv1[j] = a1 + proj_b[j];
    }
}

// ---------------------------------------------------------------------------
// Main kernel: 256 threads (8 warps), each warp handles 8 rows jointly.
// Shared: W (192x64 packed float4 pairs) 48KB + per-warp v buffers 48KB.
// ---------------------------------------------------------------------------
#define WARPS_PER_BLK 8
#define ROWS_PER_WARP 8
#define ROWS_PER_BLK  (WARPS_PER_BLK * ROWS_PER_WARP)   // 64
#define W_FLOAT4S     (96 * 32)                          // 192 k-rows packed
#define SMEM_FLOATS   (W_FLOAT4S * 4 + WARPS_PER_BLK * ROWS_PER_WARP * D_K)
#define SMEM_BYTES    (SMEM_FLOATS * 4)                  // 98304

__global__ void __launch_bounds__(256, 2)
combined_embedding_kernel(const int*   __restrict__ nbr_ids,
                          const float* __restrict__ time_feat,
                          const int*   __restrict__ bt_ids,
                          const float* __restrict__ population,
                          const int*   __restrict__ et_ids,
                          const int*   __restrict__ eq_ids,
                          const float* __restrict__ node2vec,
                          const float* __restrict__ t2v_w,
                          const float* __restrict__ t2v_b,
                          const float* __restrict__ proj_w,
                          float*       __restrict__ out) {
    extern __shared__ float smem[];
    float4* Wq  = (float4*)smem;                    // [96][32]: {W[2k][j],W[2k][j+32],W[2k+1][j],W[2k+1][j+32]}
    float*  vsh = smem + W_FLOAT4S * 4;             // per-warp [8][192]

    const int tid  = threadIdx.x;
    const int lane = tid & 31;
    const int warp = tid >> 5;

    // Stage packed W into shared (first 192 rows of proj_w = spatial + t2v)
    for (int idx = tid; idx < W_FLOAT4S; idx += 256) {
        int k2 = idx >> 5, j = idx & 31;
        const float* r0 = proj_w + (2 * k2)     * D_OUT;
        const float* r1 = proj_w + (2 * k2 + 1) * D_OUT;
        Wq[idx] = make_float4(r0[j], r0[j + 32], r1[j], r1[j + 32]);
    }
    __syncthreads();

    const int rowbase = blockIdx.x * ROWS_PER_BLK + warp * ROWS_PER_WARP;
    float* vb = vsh + warp * (ROWS_PER_WARP * D_K);

    // Per-lane t2v constants: lane handles t2v elements kk=lane (f1,e) and
    // kk=lane+32 (f1+4,e) — fixed for the whole kernel.
    const int f1 = lane >> 3;
    const int e  = lane & 7;
    const float tw1 = t2v_w[f1 * 8 + e],       tb1 = t2v_b[f1 * 8 + e];
    const float tw2 = t2v_w[(f1 + 4) * 8 + e], tb2 = t2v_b[(f1 + 4) * 8 + e];

    // --- Phase 1: build v[8][192] in shared ---
    #pragma unroll
    for (int r = 0; r < ROWS_PER_WARP; ++r) {
        int row = rowbase + r;
        int nid = nbr_ids[row];
        float4 sp = ((const float4*)node2vec)[nid * (D_NODE / 4) + lane];
        *(float4*)&vb[r * D_K + lane * 4] = sp;

        float tfv = (lane < F_DIM) ? time_feat[row * F_DIM + lane] : 0.f;
        float x1 = __shfl_sync(0xffffffffu, tfv, f1);
        float x2 = __shfl_sync(0xffffffffu, tfv, f1 + 4);
        float a1 = fmaf(x1, tw1, tb1);
        float a2 = fmaf(x2, tw2, tb2);
        float v1 = (e == 0) ? a1 : sinf(a1);
        float v2 = (e == 0) ? a2 : sinf(a2);
        vb[r * D_K + D_NODE +      lane] = v1;
        vb[r * D_K + D_NODE + 32 + lane] = v2;
    }
    __syncwarp();

    // --- Phase 2: 192x64 matvec for 8 rows, lane j owns outputs j and j+32 ---
    float acc0[ROWS_PER_WARP], acc1[ROWS_PER_WARP];
    #pragma unroll
    for (int r = 0; r < ROWS_PER_WARP; ++r) { acc0[r] = 0.f; acc1[r] = 0.f; }

    #pragma unroll 4
    for (int k4 = 0; k4 < 48; ++k4) {       // 4 k-values per iteration
        float4 wa = Wq[(2 * k4)     * 32 + lane];
        float4 wb = Wq[(2 * k4 + 1) * 32 + lane];
        #pragma unroll
        for (int r = 0; r < ROWS_PER_WARP; ++r) {
            float4 v = *(const float4*)&vb[r * D_K + 4 * k4];
            acc0[r] = fmaf(v.x, wa.x, acc0[r]);
            acc0[r] = fmaf(v.y, wa.z, acc0[r]);
            acc0[r] = fmaf(v.z, wb.x, acc0[r]);
            acc0[r] = fmaf(v.w, wb.z, acc0[r]);
            acc1[r] = fmaf(v.x, wa.y, acc1[r]);
            acc1[r] = fmaf(v.y, wa.w, acc1[r]);
            acc1[r] = fmaf(v.z, wb.y, acc1[r]);
            acc1[r] = fmaf(v.w, wb.w, acc1[r]);
        }
    }

    // --- Epilogue: add pre-projected lookup contributions, store ---
    #pragma unroll
    for (int r = 0; r < ROWS_PER_WARP; ++r) {
        int row = rowbase + r;
        int s   = row & (S_DIM - 1);
        float c = g_counts_sum[s];
        float p = population[row];
        int bt = bt_ids[row], et = et_ids[row], eq = eq_ids[row];

        float o0 = acc0[r]
                 + c * g_btype_proj[bt * D_OUT + lane]
                 + g_etype_proj[et * D_OUT + lane]
                 + g_equip_proj[eq * D_OUT + lane]
                 + p * g_pv0[lane] + g_pv1[lane];
        float o1 = acc1[r]
                 + c * g_btype_proj[bt * D_OUT + 32 + lane]
                 + g_etype_proj[et * D_OUT + 32 + lane]
                 + g_equip_proj[eq * D_OUT + 32 + lane]
                 + p * g_pv0[32 + lane] + g_pv1[32 + lane];

        out[row * D_OUT +      lane] = o0;
        out[row * D_OUT + 32 + lane] = o1;
    }
}

// ---------------------------------------------------------------------------
extern "C" void kernel_launch(void* const* d_in, const int* in_sizes, int n_in,
                              void* d_out, int out_size) {
    const int*   nbr     = (const int*)  d_in[0];
    const float* tfeat   = (const float*)d_in[1];
    const int*   bt      = (const int*)  d_in[2];
    const float* counts  = (const float*)d_in[3];
    const float* pop     = (const float*)d_in[4];
    const int*   et      = (const int*)  d_in[5];
    const int*   eq      = (const int*)  d_in[6];
    const float* n2v     = (const float*)d_in[7];
    const float* t2vw    = (const float*)d_in[8];
    const float* t2vb    = (const float*)d_in[9];
    const float* btt     = (const float*)d_in[10];
    const float* popw    = (const float*)d_in[11];
    const float* popb    = (const float*)d_in[12];
    const float* ett     = (const float*)d_in[13];
    const float* eqt     = (const float*)d_in[14];
    const float* pw      = (const float*)d_in[15];
    const float* pb      = (const float*)d_in[16];
    float*       out     = (float*)d_out;

    counts_kernel<<<(S_DIM + 255) / 256, 256>>>(counts);
    precompute_tables<<<N_BT + N_ET + N_EQ + 1, 64>>>(btt, ett, eqt, popw, popb, pw, pb);

    cudaFuncSetAttribute(combined_embedding_kernel,
                         cudaFuncAttributeMaxDynamicSharedMemorySize, SMEM_BYTES);
    combined_embedding_kernel<<<ROWS / ROWS_PER_BLK, 256, SMEM_BYTES>>>(
        nbr, tfeat, bt, pop, et, eq, n2v, t2vw, t2vb, pw, out);
}

// round 2
// speedup vs baseline: 1.1520x; 1.1520x over previous
#include <cuda_runtime.h>
#include <cuda_bf16.h>
#include <math.h>

// Problem constants
#define B_DIM     32
#define S_DIM     2048
#define ROWS      (B_DIM * S_DIM)      // 65536
#define F_DIM     8
#define D_NODE    128
#define D_T2V     64
#define D_K       (D_NODE + D_T2V)     // 192
#define D_OUT     64
#define N_BT      64
#define N_ET      50
#define N_EQ      100

#define OFF_BT    192
#define OFF_POP   224
#define OFF_ET    240
#define OFF_EQ    272

// Scratch (no cudaMalloc allowed)
__device__ float g_btype_proj[N_BT * D_OUT];
__device__ float g_etype_proj[N_ET * D_OUT];
__device__ float g_equip_proj[N_EQ * D_OUT];
__device__ float g_pv0[D_OUT];   // pop_w @ W_pop
__device__ float g_pv1[D_OUT];   // pop_b @ W_pop + proj_b

// ---------------------------------------------------------------------------
// f32x2 packed helpers (Blackwell FFMA2 path — PTX-only)
// ---------------------------------------------------------------------------
__device__ __forceinline__ unsigned long long fma2(unsigned long long a,
                                                   unsigned long long b,
                                                   unsigned long long c) {
    unsigned long long d;
    asm("fma.rn.f32x2 %0, %1, %2, %3;" : "=l"(d) : "l"(a), "l"(b), "l"(c));
    return d;
}
__device__ __forceinline__ unsigned long long bcast2(float x) {
    unsigned long long d;
    unsigned int xi = __float_as_uint(x);
    asm("mov.b64 %0, {%1, %1};" : "=l"(d) : "r"(xi));
    return d;
}
__device__ __forceinline__ void unpack2(unsigned long long v, float& lo, float& hi) {
    unsigned int a, b;
    asm("mov.b64 {%0, %1}, %2;" : "=r"(a), "=r"(b) : "l"(v));
    lo = __uint_as_float(a);
    hi = __uint_as_float(b);
}

// ---------------------------------------------------------------------------
// Precompute: project small-vocab tables into output space (64-dim)
// grid = 64 + 50 + 100 + 1 = 215 blocks of 64 threads
// ---------------------------------------------------------------------------
__global__ void precompute_tables(const float* __restrict__ btype_table,
                                  const float* __restrict__ etype_table,
                                  const float* __restrict__ equip_table,
                                  const float* __restrict__ pop_w,
                                  const float* __restrict__ pop_b,
                                  const float* __restrict__ proj_w,
                                  const float* __restrict__ proj_b) {
    int j = threadIdx.x;
    int n = blockIdx.x;
    if (n < N_BT) {
        float a = 0.f;
        #pragma unroll
        for (int d = 0; d < 32; ++d)
            a += btype_table[n * 32 + d] * proj_w[(OFF_BT + d) * D_OUT + j];
        g_btype_proj[n * D_OUT + j] = a;
    } else if (n < N_BT + N_ET) {
        int m = n - N_BT;
        float a = 0.f;
        #pragma unroll
        for (int d = 0; d < 32; ++d)
            a += etype_table[m * 32 + d] * proj_w[(OFF_ET + d) * D_OUT + j];
        g_etype_proj[m * D_OUT + j] = a;
    } else if (n < N_BT + N_ET + N_EQ) {
        int m = n - N_BT - N_ET;
        float a = 0.f;
        #pragma unroll
        for (int d = 0; d < 32; ++d)
            a += equip_table[m * 32 + d] * proj_w[(OFF_EQ + d) * D_OUT + j];
        g_equip_proj[m * D_OUT + j] = a;
    } else {
        float a0 = 0.f, a1 = 0.f;
        #pragma unroll
        for (int d = 0; d < 16; ++d) {
            float w = proj_w[(OFF_POP + d) * D_OUT + j];
            a0 += pop_w[d] * w;
            a1 += pop_b[d] * w;
        }
        g_pv0[j] = a0;
        g_pv1[j] = a1 + proj_b[j];
    }
}

// ---------------------------------------------------------------------------
// Main kernel: 256 threads (8 warps), each warp handles 8 rows jointly.
//
// smem layout (floats):
//   Wq      [96][32] float4 packed: {W[2k][j], W[2k][j+32], W[2k+1][j], W[2k+1][j+32]}
//   vQ      per warp, 1728 floats, packed layout:
//           off(k,r) = (k/2)*18 + (r/2)*4 + (k&1)*2 + (r&1)
//           => b64 at (k/2)*18 + (k&1)*2 + rp*4 is (v[2rp][k], v[2rp+1][k])
//   counts_s[64]
// ---------------------------------------------------------------------------
#define WARPS_PER_BLK 8
#define ROWS_PER_WARP 8
#define ROWS_PER_BLK  64
#define W_FLOAT4S     (96 * 32)                 // 3072 float4 = 12288 floats
#define VWARP_FLOATS  1728
#define SMEM_FLOATS   (W_FLOAT4S * 4 + WARPS_PER_BLK * VWARP_FLOATS + 64)
#define SMEM_BYTES    (SMEM_FLOATS * 4)         // 104704

__global__ void __launch_bounds__(256, 2)
combined_embedding_kernel(const int*   __restrict__ nbr_ids,
                          const float* __restrict__ time_feat,
                          const int*   __restrict__ bt_ids,
                          const float* __restrict__ counts,
                          const float* __restrict__ population,
                          const int*   __restrict__ et_ids,
                          const int*   __restrict__ eq_ids,
                          const float* __restrict__ node2vec,
                          const float* __restrict__ t2v_w,
                          const float* __restrict__ t2v_b,
                          const float* __restrict__ proj_w,
                          float*       __restrict__ out) {
    extern __shared__ float smem[];
    float4* Wq       = (float4*)smem;
    float*  vsh      = smem + W_FLOAT4S * 4;
    float*  counts_s = smem + W_FLOAT4S * 4 + WARPS_PER_BLK * VWARP_FLOATS;

    const int tid  = threadIdx.x;
    const int lane = tid & 31;
    const int warp = tid >> 5;
    const int rowbase = blockIdx.x * ROWS_PER_BLK + warp * ROWS_PER_WARP;

    // --- counts_sum for this block's 64 s-values (folded-in counts kernel) ---
    {
        int s_local  = tid >> 2;            // 4 threads per s
        int q        = tid & 3;             // each sums 8 of 32 b's
        int s_global = ((blockIdx.x * ROWS_PER_BLK) & (S_DIM - 1)) + s_local;
        float p = 0.f;
        #pragma unroll
        for (int i = 0; i < 8; ++i)
            p += counts[(q * 8 + i) * S_DIM + s_global];
        p += __shfl_xor_sync(0xffffffffu, p, 1);
        p += __shfl_xor_sync(0xffffffffu, p, 2);
        if (q == 0) counts_s[s_local] = p;
    }

    // --- stage packed W into shared (first 192 rows of proj_w) ---
    for (int idx = tid; idx < W_FLOAT4S; idx += 256) {
        int k2 = idx >> 5, j = idx & 31;
        const float* r0 = proj_w + (2 * k2)     * D_OUT;
        const float* r1 = proj_w + (2 * k2 + 1) * D_OUT;
        Wq[idx] = make_float4(r0[j], r0[j + 32], r1[j], r1[j + 32]);
    }
    __syncthreads();

    float* vb = vsh + warp * VWARP_FLOATS;

    // per-lane t2v constants: lane handles t2v elems kk=lane and kk=lane+32
    const int f1 = lane >> 3;
    const int e  = lane & 7;
    const float tw1 = t2v_w[f1 * 8 + e],       tb1 = t2v_b[f1 * 8 + e];
    const float tw2 = t2v_w[(f1 + 4) * 8 + e], tb2 = t2v_b[(f1 + 4) * 8 + e];

    // --- Phase 1: build vQ (transposed, row-pair packed) ---
    #pragma unroll
    for (int r = 0; r < ROWS_PER_WARP; ++r) {
        int row = rowbase + r;
        int nid = nbr_ids[row];
        float4 sp = ((const float4*)node2vec)[nid * (D_NODE / 4) + lane];
        // k = 4*lane + i
        int rp4 = ((r >> 1) << 2) + (r & 1);
        int b0  = (2 * lane) * 18 + rp4;
        vb[b0]      = sp.x;   // k=4l   (even)
        vb[b0 + 2]  = sp.y;   // k=4l+1 (odd)
        vb[b0 + 18] = sp.z;   // k=4l+2
        vb[b0 + 20] = sp.w;   // k=4l+3

        float tfv = (lane < F_DIM) ? time_feat[row * F_DIM + lane] : 0.f;
        float x1 = __shfl_sync(0xffffffffu, tfv, f1);
        float x2 = __shfl_sync(0xffffffffu, tfv, f1 + 4);
        float a1 = fmaf(x1, tw1, tb1);
        float a2 = fmaf(x2, tw2, tb2);
        float v1 = (e == 0) ? a1 : __sinf(a1);
        float v2 = (e == 0) ? a2 : __sinf(a2);
        // k1 = 128 + lane, k2v = 160 + lane
        vb[(64 + (lane >> 1)) * 18 + rp4 + ((lane & 1) << 1)] = v1;
        vb[(80 + (lane >> 1)) * 18 + rp4 + ((lane & 1) << 1)] = v2;
    }
    __syncwarp();

    // --- Phase 2: 192x64 matvec for 8 rows via packed FFMA2 ---
    // acc0[rp] = (out_j[2rp], out_j[2rp+1]); acc1 same for j+32
    unsigned long long acc0[4] = {0ull, 0ull, 0ull, 0ull};
    unsigned long long acc1[4] = {0ull, 0ull, 0ull, 0ull};

    #pragma unroll 2
    for (int k2 = 0; k2 < 96; ++k2) {
        float4 w = Wq[k2 * 32 + lane];
        unsigned long long wx = bcast2(w.x);   // W[2k2][j]
        unsigned long long wy = bcast2(w.y);   // W[2k2][j+32]
        unsigned long long wz = bcast2(w.z);   // W[2k2+1][j]
        unsigned long long wwp = bcast2(w.w);  // W[2k2+1][j+32]
        const float* base = vb + k2 * 18;
        #pragma unroll
        for (int rp = 0; rp < 4; ++rp) {
            unsigned long long va  = *(const unsigned long long*)(base + rp * 4);
            unsigned long long vbq = *(const unsigned long long*)(base + rp * 4 + 2);
            acc0[rp] = fma2(va,  wx,  acc0[rp]);
            acc1[rp] = fma2(va,  wy,  acc1[rp]);
            acc0[rp] = fma2(vbq, wz,  acc0[rp]);
            acc1[rp] = fma2(vbq, wwp, acc1[rp]);
        }
    }

    // --- Epilogue: add pre-projected lookup contributions, store ---
    #pragma unroll
    for (int rp = 0; rp < 4; ++rp) {
        float a0lo, a0hi, a1lo, a1hi;
        unpack2(acc0[rp], a0lo, a0hi);
        unpack2(acc1[rp], a1lo, a1hi);
        #pragma unroll
        for (int h = 0; h < 2; ++h) {
            int r   = 2 * rp + h;
            int row = rowbase + r;
            float accj  = h ? a0hi : a0lo;
            float accj2 = h ? a1hi : a1lo;
            float c = counts_s[row & (ROWS_PER_BLK - 1)];
            float p = population[row];
            int bt = bt_ids[row], et = et_ids[row], eq = eq_ids[row];

            float o0 = accj
                     + c * g_btype_proj[bt * D_OUT + lane]
                     + g_etype_proj[et * D_OUT + lane]
                     + g_equip_proj[eq * D_OUT + lane]
                     + p * g_pv0[lane] + g_pv1[lane];
            float o1 = accj2
                     + c * g_btype_proj[bt * D_OUT + 32 + lane]
                     + g_etype_proj[et * D_OUT + 32 + lane]
                     + g_equip_proj[eq * D_OUT + 32 + lane]
                     + p * g_pv0[32 + lane] + g_pv1[32 + lane];

            out[row * D_OUT +      lane] = o0;
            out[row * D_OUT + 32 + lane] = o1;
        }
    }
}

// ---------------------------------------------------------------------------
extern "C" void kernel_launch(void* const* d_in, const int* in_sizes, int n_in,
                              void* d_out, int out_size) {
    const int*   nbr     = (const int*)  d_in[0];
    const float* tfeat   = (const float*)d_in[1];
    const int*   bt      = (const int*)  d_in[2];
    const float* counts  = (const float*)d_in[3];
    const float* pop     = (const float*)d_in[4];
    const int*   et      = (const int*)  d_in[5];
    const int*   eq      = (const int*)  d_in[6];
    const float* n2v     = (const float*)d_in[7];
    const float* t2vw    = (const float*)d_in[8];
    const float* t2vb    = (const float*)d_in[9];
    const float* btt     = (const float*)d_in[10];
    const float* popw    = (const float*)d_in[11];
    const float* popb    = (const float*)d_in[12];
    const float* ett     = (const float*)d_in[13];
    const float* eqt     = (const float*)d_in[14];
    const float* pw      = (const float*)d_in[15];
    const float* pb      = (const float*)d_in[16];
    float*       out     = (float*)d_out;

    precompute_tables<<<N_BT + N_ET + N_EQ + 1, 64>>>(btt, ett, eqt, popw, popb, pw, pb);

    cudaFuncSetAttribute(combined_embedding_kernel,
                         cudaFuncAttributeMaxDynamicSharedMemorySize, SMEM_BYTES);
    combined_embedding_kernel<<<ROWS / ROWS_PER_BLK, 256, SMEM_BYTES>>>(
        nbr, tfeat, bt, counts, pop, et, eq, n2v, t2vw, t2vb, pw, out);
}